// round 14
// baseline (speedup 1.0000x reference)
#include <cuda_runtime.h>
#include <cuda_fp16.h>
#include <math.h>

#define Bb   8
#define Nn   576
#define Dd   512
#define Mm   16
#define Hh   8
#define BN   (Bb*Nn)      // 4608
#define KTOP 51

typedef unsigned long long u64;
typedef unsigned int u32;

__device__ __forceinline__ u32 smem_u32(const void* p) {
    u32 a; asm("{ .reg .u64 t; cvta.to.shared.u64 t, %1; cvt.u32.u64 %0, t; }"
               : "=r"(a) : "l"(p));
    return a;
}

// ---- mma.sync helpers (fp16 in, fp32 acc) ----
__device__ __forceinline__ void ldsm4(u32* r, u32 addr) {
    asm volatile("ldmatrix.sync.aligned.m8n8.x4.shared.b16 {%0,%1,%2,%3}, [%4];"
                 : "=r"(r[0]), "=r"(r[1]), "=r"(r[2]), "=r"(r[3]) : "r"(addr));
}
__device__ __forceinline__ void ldsm4t(u32* r, u32 addr) {
    asm volatile("ldmatrix.sync.aligned.m8n8.x4.trans.shared.b16 {%0,%1,%2,%3}, [%4];"
                 : "=r"(r[0]), "=r"(r[1]), "=r"(r[2]), "=r"(r[3]) : "r"(addr));
}
__device__ __forceinline__ void mma16816(float* c, const u32* a, const u32* b) {
    asm volatile(
        "mma.sync.aligned.m16n8k16.row.col.f32.f16.f16.f32 "
        "{%0,%1,%2,%3}, {%4,%5,%6,%7}, {%8,%9}, {%0,%1,%2,%3};"
        : "+f"(c[0]), "+f"(c[1]), "+f"(c[2]), "+f"(c[3])
        : "r"(a[0]), "r"(a[1]), "r"(a[2]), "r"(a[3]), "r"(b[0]), "r"(b[1]));
}
__device__ __forceinline__ u32 h2pack(float x, float y) {
    __half2 h = __floats2half2_rn(x, y);
    return *(u32*)&h;
}

// ---- cp.async ----
__device__ __forceinline__ void cpa16(u32 saddr, const void* g) {
    asm volatile("cp.async.cg.shared.global [%0], [%1], 16;" :: "r"(saddr), "l"(g));
}
#define CP_COMMIT() asm volatile("cp.async.commit_group;" ::: "memory")
#define CP_WAIT0()  asm volatile("cp.async.wait_group 0;" ::: "memory")

// ---- scratch (fp16) ----
__device__ __half g_qkv[BN * 3 * Dd];   // qkv (Q pre-scaled 1/8)
__device__ __half g_F16[BN * Dd];
__device__ __half g_wq [3*Dd*Dd];
__device__ __half g_wo [Dd*Dd];
__device__ __half g_w1 [Dd*Dd];
__device__ __half g_at [BN * Dd];
__device__ __half g_fe [BN * Dd];
__device__ float  g_h  [BN * Dd];

// ============================================================
// One-launch fp32 -> fp16 convert over 4 tensors
// ============================================================
#define SEG0 589824
#define SEG1 (SEG0 + 196608)
#define SEG2 (SEG1 + 65536)
#define SEG3 (SEG2 + 65536)

__global__ __launch_bounds__(256) void cvt_all_kernel(
    const float* __restrict__ F,    const float* __restrict__ Wqkv,
    const float* __restrict__ Wout, const float* __restrict__ w1,
    __half* __restrict__ F16, __half* __restrict__ wq,
    __half* __restrict__ wo,  __half* __restrict__ w1h)
{
    int i = blockIdx.x * 256 + threadIdx.x;
    if (i >= SEG3) return;
    const float* src; __half* dst; int j;
    if (i < SEG0)      { src = F;    dst = F16; j = i; }
    else if (i < SEG1) { src = Wqkv; dst = wq;  j = i - SEG0; }
    else if (i < SEG2) { src = Wout; dst = wo;  j = i - SEG1; }
    else               { src = w1;   dst = w1h; j = i - SEG2; }
    float4 v = reinterpret_cast<const float4*>(src)[j];
    u32 h0 = h2pack(v.x, v.y), h1 = h2pack(v.z, v.w);
    reinterpret_cast<uint2*>(dst)[j] = make_uint2(h0, h1);
}

// ============================================================
// Tensor-core HGEMM v2: 64x128 tile, 256 threads (8 warps 2x4),
// 2 CTAs/SM. cp.async 2-stage, K-chunk 32, 80B rows.
// ============================================================
#define GROWB 80
#define GA_BYTES (64 * GROWB)            // 5120
#define GB_OFF   GA_BYTES
#define GBUFSZ   (GA_BYTES + 128 * GROWB)  // 15360
#define GEMM_SMEM (2 * GBUFSZ)           // 30720

__global__ __launch_bounds__(256, 2) void sgemm_tc(
    const __half* __restrict__ A, const __half* __restrict__ B,
    const float* __restrict__ bias, const float* __restrict__ residual,
    float* __restrict__ C, __half* __restrict__ S16,
    int qsplit, int K, int N)
{
    extern __shared__ unsigned char smem[];
    const u32 sb = smem_u32(smem);

    const int tid = threadIdx.x;
    const int wid = tid >> 5, lid = tid & 31;
    const int rowBase = blockIdx.y * 64;
    const int colBase = blockIdx.x * 128;
    const int warp_m = (wid >> 2) * 32;
    const int warp_n = (wid & 3) * 32;

    // loaders: A 256 chunks (1/thread), B 512 chunks (2/thread)
    const int lrow = tid >> 2;            // 0..63
    const int lc4  = tid & 3;
    const u32 soA  = (u32)lrow * GROWB + (u32)lc4 * 16;
    const u32 soB0 = GB_OFF + soA;
    const u32 soB1 = soB0 + 64u * GROWB;
    const char* pA  = (const char*)A + ((size_t)(rowBase + lrow) * K) * 2 + lc4 * 16;
    const char* pB0 = (const char*)B + ((size_t)(colBase + lrow) * K) * 2 + lc4 * 16;
    const char* pB1 = (const char*)B + ((size_t)(colBase + lrow + 64) * K) * 2 + lc4 * 16;

    const int a_row = warp_m + (lid & 15);
    const u32 a_kb  = (u32)(lid >> 4) * 16;
    const int b_n   = warp_n + (lid & 7) + ((lid >> 4) << 3);
    const u32 b_kb  = (u32)((lid >> 3) & 1) * 16;

    float acc[2][4][4];
    #pragma unroll
    for (int i = 0; i < 2; i++)
        #pragma unroll
        for (int j = 0; j < 4; j++)
            #pragma unroll
            for (int q = 0; q < 4; q++) acc[i][j][q] = 0.f;

    const int nChunk = K >> 5;
    {
        cpa16(sb + soA,  pA);
        cpa16(sb + soB0, pB0);
        cpa16(sb + soB1, pB1);
        CP_COMMIT();
    }

    for (int c = 0; c < nChunk; c++) {
        CP_WAIT0();
        __syncthreads();
        if (c + 1 < nChunk) {
            u32 d = sb + (u32)((c + 1) & 1) * GBUFSZ;
            size_t kb = (size_t)(c + 1) * 64;
            cpa16(d + soA,  pA  + kb);
            cpa16(d + soB0, pB0 + kb);
            cpa16(d + soB1, pB1 + kb);
            CP_COMMIT();
        }

        const u32 bufo = (u32)(c & 1) * GBUFSZ;
        #pragma unroll
        for (int ks = 0; ks < 2; ks++) {
            const u32 kso = (u32)ks * 32;
            u32 bfr[2][4];
            #pragma unroll
            for (int np = 0; np < 2; np++) {
                u32 ba = sb + bufo + GB_OFF + (u32)(b_n + np * 16) * GROWB + kso + b_kb;
                ldsm4(bfr[np], ba);
            }
            #pragma unroll
            for (int mt = 0; mt < 2; mt++) {
                u32 aa = sb + bufo + (u32)(a_row + mt * 16) * GROWB + kso + a_kb;
                u32 afr[4];
                ldsm4(afr, aa);
                #pragma unroll
                for (int nt = 0; nt < 4; nt++)
                    mma16816(acc[mt][nt], afr, &bfr[nt >> 1][(nt & 1) * 2]);
            }
        }
    }

    const int frow = lid >> 2;
    const int fcol = (lid & 3) * 2;
    #pragma unroll
    for (int mt = 0; mt < 2; mt++) {
        #pragma unroll
        for (int nt = 0; nt < 4; nt++) {
            int col = colBase + warp_n + nt * 8 + fcol;
            float2 bi = *reinterpret_cast<const float2*>(bias + col);
            #pragma unroll
            for (int half = 0; half < 2; half++) {
                int r = rowBase + warp_m + mt * 16 + frow + half * 8;
                float2 o;
                o.x = acc[mt][nt][half * 2 + 0] + bi.x;
                o.y = acc[mt][nt][half * 2 + 1] + bi.y;
                if (residual) {
                    float2 rv = *reinterpret_cast<const float2*>(residual + (size_t)r * N + col);
                    o.x += rv.x; o.y += rv.y;
                }
                if (C)
                    *reinterpret_cast<float2*>(C + (size_t)r * N + col) = o;
                if (S16) {
                    float sc = (qsplit && col < 512) ? 0.125f : 1.0f;
                    *reinterpret_cast<u32*>(S16 + (size_t)r * N + col) =
                        h2pack(o.x * sc, o.y * sc);
                }
            }
        }
    }
}

// ============================================================
// Tensor-core flash attention, plain fp16 (R13-passing, unchanged)
// ============================================================
#define ROWB 144
#define QT 96
#define KV_K 0
#define KV_V 9216
#define KVBUF 18432
#define AQ   (2 * KVBUF)
#define ATTN_SMEM (2 * KVBUF + 13824)

__global__ __launch_bounds__(192) void attn_tc(
    const __half* __restrict__ qkv, __half* __restrict__ oat)
{
    extern __shared__ unsigned char smem[];
    const u32 sb = smem_u32(smem);

    const int tid = threadIdx.x;
    const int wid = tid >> 5, lid = tid & 31;
    const int bh = blockIdx.y;
    const int b = bh >> 3, h = bh & 7;
    const int q0 = blockIdx.x * QT;

    const __half* qp = qkv + (size_t)(b * Nn + q0) * 1536 + h * 64;
    const __half* kp = qkv + (size_t)(b * Nn) * 1536 + 512  + h * 64;
    const __half* vp = qkv + (size_t)(b * Nn) * 1536 + 1024 + h * 64;

    for (int s = tid; s < 512; s += 192) {
        int row = s >> 3, c8 = s & 7;
        size_t go = (size_t)row * 1536 + c8 * 8;
        u32 so = sb + (u32)row * ROWB + (u32)c8 * 16;
        cpa16(so + KV_K, kp + go);
        cpa16(so + KV_V, vp + go);
    }
    #pragma unroll
    for (int it = 0; it < 4; it++) {
        int s = tid + it * 192;
        int row = s >> 3, c8 = s & 7;
        size_t go = (size_t)row * 1536 + c8 * 8;
        cpa16(sb + AQ + (u32)row * ROWB + (u32)c8 * 16, qp + go);
    }
    CP_COMMIT();
    CP_WAIT0();
    __syncthreads();

    u32 qf[4][4];
    {
        const int a_row = (wid << 4) + (lid & 15);
        const u32 a_kb = (u32)(lid >> 4) * 16;
        #pragma unroll
        for (int kt = 0; kt < 4; kt++)
            ldsm4(qf[kt], sb + AQ + (u32)a_row * ROWB + (u32)kt * 32 + a_kb);
    }

    float m_lo = -1e30f, m_hi = -1e30f, l_lo = 0.f, l_hi = 0.f;
    float oacc[8][4];
    #pragma unroll
    for (int j = 0; j < 8; j++)
        #pragma unroll
        for (int q = 0; q < 4; q++) oacc[j][q] = 0.f;

    const int kb_row = (lid & 7) + ((lid >> 4) << 3);
    const u32 kb_kb  = (u32)((lid >> 3) & 1) * 16;
    const int vb_key = (lid & 7) + (((lid >> 3) & 1) << 3);
    const u32 vb_db  = (u32)(lid >> 4) * 16;

    const int nChunk = Nn / 64;
    for (int c = 0; c < nChunk; c++) {
        if (c + 1 < nChunk) {
            const u32 nb = sb + (u32)((c + 1) & 1) * KVBUF;
            const int kc1 = (c + 1) * 64;
            for (int s = tid; s < 512; s += 192) {
                int row = s >> 3, c8 = s & 7;
                size_t go = (size_t)(kc1 + row) * 1536 + c8 * 8;
                u32 so = nb + (u32)row * ROWB + (u32)c8 * 16;
                cpa16(so + KV_K, kp + go);
                cpa16(so + KV_V, vp + go);
            }
        }
        CP_COMMIT();

        const u32 bufb = sb + (u32)(c & 1) * KVBUF;

        float sacc[8][4];
        #pragma unroll
        for (int j = 0; j < 8; j++)
            #pragma unroll
            for (int q = 0; q < 4; q++) sacc[j][q] = 0.f;

        #pragma unroll
        for (int kt = 0; kt < 4; kt++) {
            #pragma unroll
            for (int ng = 0; ng < 4; ng++) {
                u32 ka = bufb + KV_K + (u32)(ng * 16 + kb_row) * ROWB + (u32)kt * 32 + kb_kb;
                u32 kf[4];
                ldsm4(kf, ka);
                mma16816(sacc[2 * ng + 0], qf[kt], &kf[0]);
                mma16816(sacc[2 * ng + 1], qf[kt], &kf[2]);
            }
        }

        float mx_lo = -1e30f, mx_hi = -1e30f;
        #pragma unroll
        for (int j = 0; j < 8; j++) {
            mx_lo = fmaxf(mx_lo, fmaxf(sacc[j][0], sacc[j][1]));
            mx_hi = fmaxf(mx_hi, fmaxf(sacc[j][2], sacc[j][3]));
        }
        #pragma unroll
        for (int o = 1; o <= 2; o <<= 1) {
            mx_lo = fmaxf(mx_lo, __shfl_xor_sync(0xffffffffu, mx_lo, o));
            mx_hi = fmaxf(mx_hi, __shfl_xor_sync(0xffffffffu, mx_hi, o));
        }
        float mn_lo = fmaxf(m_lo, mx_lo), mn_hi = fmaxf(m_hi, mx_hi);
        float corr_lo = __expf(m_lo - mn_lo), corr_hi = __expf(m_hi - mn_hi);
        float rs_lo = 0.f, rs_hi = 0.f;
        #pragma unroll
        for (int j = 0; j < 8; j++) {
            sacc[j][0] = __expf(sacc[j][0] - mn_lo);
            sacc[j][1] = __expf(sacc[j][1] - mn_lo);
            sacc[j][2] = __expf(sacc[j][2] - mn_hi);
            sacc[j][3] = __expf(sacc[j][3] - mn_hi);
            rs_lo += sacc[j][0] + sacc[j][1];
            rs_hi += sacc[j][2] + sacc[j][3];
        }
        #pragma unroll
        for (int o = 1; o <= 2; o <<= 1) {
            rs_lo += __shfl_xor_sync(0xffffffffu, rs_lo, o);
            rs_hi += __shfl_xor_sync(0xffffffffu, rs_hi, o);
        }
        l_lo = l_lo * corr_lo + rs_lo;
        l_hi = l_hi * corr_hi + rs_hi;
        m_lo = mn_lo; m_hi = mn_hi;
        #pragma unroll
        for (int j = 0; j < 8; j++) {
            oacc[j][0] *= corr_lo; oacc[j][1] *= corr_lo;
            oacc[j][2] *= corr_hi; oacc[j][3] *= corr_hi;
        }

        #pragma unroll
        for (int kt = 0; kt < 4; kt++) {
            const int j0 = 2 * kt, j1 = 2 * kt + 1;
            u32 ap[4];
            ap[0] = h2pack(sacc[j0][0], sacc[j0][1]);
            ap[1] = h2pack(sacc[j0][2], sacc[j0][3]);
            ap[2] = h2pack(sacc[j1][0], sacc[j1][1]);
            ap[3] = h2pack(sacc[j1][2], sacc[j1][3]);
            #pragma unroll
            for (int ng = 0; ng < 4; ng++) {
                u32 va = bufb + KV_V + (u32)(kt * 16 + vb_key) * ROWB + (u32)ng * 32 + vb_db;
                u32 vf[4];
                ldsm4t(vf, va);
                mma16816(oacc[2 * ng + 0], ap, &vf[0]);
                mma16816(oacc[2 * ng + 1], ap, &vf[2]);
            }
        }

        CP_WAIT0();
        __syncthreads();
    }

    const float inv_lo = 1.f / l_lo, inv_hi = 1.f / l_hi;
    const int r_lo = q0 + (wid << 4) + (lid >> 2);
    const int cb = h * 64 + (lid & 3) * 2;
    #pragma unroll
    for (int j = 0; j < 8; j++) {
        int col = cb + j * 8;
        *reinterpret_cast<u32*>(oat + (size_t)(b * Nn + r_lo) * Dd + col) =
            h2pack(oacc[j][0] * inv_lo, oacc[j][1] * inv_lo);
        *reinterpret_cast<u32*>(oat + (size_t)(b * Nn + r_lo + 8) * Dd + col) =
            h2pack(oacc[j][2] * inv_hi, oacc[j][3] * inv_hi);
    }
}

// ============================================================
// FUSED final stage v2: 4 rows/block, w2+templates cached in smem.
// LN -> GELU -> comp -> outer -> top-51 -> write.
// ============================================================
#define RPB 4
#define FK_W2  0
#define FK_TP  32768
#define FK_QO  65536
#define FK_S   (FK_QO + 34816)     // 100352
#define FK_F   (FK_S + 2048)
#define FK_RED (FK_F + 2048)
#define FK_CS  (FK_RED + 128)
#define FK_SMEM (FK_CS + 64)       // 104640

__global__ __launch_bounds__(512) void ln_outer_topk_kernel(
    const float* __restrict__ hsrc,
    const float* __restrict__ ln_g, const float* __restrict__ ln_b,
    const float* __restrict__ w2,  const float* __restrict__ b2,
    const float* __restrict__ F, const float* __restrict__ templates,
    float* __restrict__ out)
{
    extern __shared__ unsigned char sm[];
    float* w2S  = (float*)(sm + FK_W2);
    float* tpS  = (float*)(sm + FK_TP);
    float* Qout = (float*)(sm + FK_QO);
    float* s    = (float*)(sm + FK_S);
    float* Frow = (float*)(sm + FK_F);
    float* red  = (float*)(sm + FK_RED);
    float* cs   = (float*)(sm + FK_CS);

    const int tid = threadIdx.x;
    const int m = tid >> 5, lid = tid & 31;

    // cache w2 + templates (8192 floats each)
    #pragma unroll
    for (int i = tid; i < 2048; i += 512) {
        reinterpret_cast<float4*>(w2S)[i] = reinterpret_cast<const float4*>(w2)[i];
        reinterpret_cast<float4*>(tpS)[i] = reinterpret_cast<const float4*>(templates)[i];
    }

    for (int r = 0; r < RPB; r++) {
        const int row = blockIdx.x * RPB + r;
        __syncthreads();   // w2S/tpS ready (iter 0); Qout drained (iters >0)

        float x = hsrc[(size_t)row * 512 + tid];
        s[tid] = x;
        Frow[tid] = F[(size_t)row * 512 + tid];

        float sum = x, sq = x * x;
        #pragma unroll
        for (int o = 16; o >= 1; o >>= 1) {
            sum += __shfl_xor_sync(0xffffffffu, sum, o);
            sq  += __shfl_xor_sync(0xffffffffu, sq,  o);
        }
        if (lid == 0) { red[m] = sum; red[m + 16] = sq; }
        __syncthreads();
        if (tid == 0) {
            float S = 0.f, Q = 0.f;
            #pragma unroll
            for (int i = 0; i < 16; i++) { S += red[i]; Q += red[i + 16]; }
            red[0] = S * (1.f / 512.f);
            red[16] = Q * (1.f / 512.f);
        }
        __syncthreads();
        const float mean = red[0];
        const float rstd = rsqrtf(red[16] - mean * mean + 1e-5f);

        float g = (x - mean) * rstd * ln_g[tid] + ln_b[tid];
        g = 0.5f * g * (1.f + erff(g * 0.70710678118f));
        __syncthreads();
        s[tid] = g;
        __syncthreads();

        {
            float p = 0.f;
            const float* wrow = w2S + m * 512;
            #pragma unroll
            for (int i = 0; i < 16; i++) {
                int e = lid + 32 * i;
                p += s[e] * wrow[e];
            }
            #pragma unroll
            for (int o = 16; o >= 1; o >>= 1)
                p += __shfl_xor_sync(0xffffffffu, p, o);
            if (lid == 0) cs[m] = p + b2[m];
        }
        __syncthreads();

        const float c = cs[m];
        float    qv[16];
        unsigned key[16];
        unsigned mx = 0;
        #pragma unroll
        for (int i = 0; i < 16; i++) {
            int d = lid + 32 * i;
            float q = Frow[d] * tpS[m * 512 + d] * c;
            qv[i]  = q;
            key[i] = __float_as_uint(fabsf(q));
            mx = max(mx, key[i]);
        }
        #pragma unroll
        for (int o = 16; o >= 1; o >>= 1)
            mx = max(mx, __shfl_xor_sync(0xffffffffu, mx, o));

        unsigned prefix = 0;
        int bit = 31 - __clz(mx | 1u);
        for (; bit >= 0; bit--) {
            unsigned test = prefix | (1u << bit);
            int cnt = 0;
            #pragma unroll
            for (int i = 0; i < 16; i++) cnt += (key[i] >= test);
            cnt = __reduce_add_sync(0xffffffffu, cnt);
            if (cnt >= KTOP) {
                prefix = test;
                if (cnt == KTOP) break;
            }
        }

        #pragma unroll
        for (int i = 0; i < 16; i++) {
            int d = lid + 32 * i;
            Qout[d * 17 + m] = (key[i] >= prefix) ? qv[i] : 0.f;
        }
        __syncthreads();

        float* ob = out + (size_t)row * (512 * 16);
        #pragma unroll
        for (int i = 0; i < 16; i++) {
            int e = tid + 512 * i;
            ob[e] = Qout[(e >> 4) * 17 + (e & 15)];
        }
    }
}

// ============================================================
extern "C" void kernel_launch(void* const* d_in, const int* in_sizes, int n_in,
                              void* d_out, int out_size) {
    const float* F    = (const float*)d_in[0];
    const float* Wqkv = (const float*)d_in[1];
    const float* bqkv = (const float*)d_in[2];
    const float* Wout = (const float*)d_in[3];
    const float* bout = (const float*)d_in[4];
    const float* w1   = (const float*)d_in[5];
    const float* b1   = (const float*)d_in[6];
    const float* lng  = (const float*)d_in[7];
    const float* lnb  = (const float*)d_in[8];
    const float* w2   = (const float*)d_in[9];
    const float* b2   = (const float*)d_in[10];
    const float* tmpl = (const float*)d_in[11];
    float* out = (float*)d_out;

    __half *qkv16, *F16, *wq, *wo, *w1h, *at16, *fe16;
    float *hbuf;
    cudaGetSymbolAddress((void**)&qkv16, g_qkv);
    cudaGetSymbolAddress((void**)&F16,   g_F16);
    cudaGetSymbolAddress((void**)&wq,    g_wq);
    cudaGetSymbolAddress((void**)&wo,    g_wo);
    cudaGetSymbolAddress((void**)&w1h,   g_w1);
    cudaGetSymbolAddress((void**)&at16,  g_at);
    cudaGetSymbolAddress((void**)&fe16,  g_fe);
    cudaGetSymbolAddress((void**)&hbuf,  g_h);

    cudaFuncSetAttribute(sgemm_tc, cudaFuncAttributeMaxDynamicSharedMemorySize,
                         GEMM_SMEM);
    cudaFuncSetAttribute(attn_tc, cudaFuncAttributeMaxDynamicSharedMemorySize,
                         ATTN_SMEM);
    cudaFuncSetAttribute(ln_outer_topk_kernel,
                         cudaFuncAttributeMaxDynamicSharedMemorySize, FK_SMEM);

    cvt_all_kernel<<<(SEG3 + 255) / 256, 256>>>(F, Wqkv, Wout, w1, F16, wq, wo, w1h);

    // qkv = F @ Wqkv^T + bqkv -> fp16 (Q scaled 1/8)
    sgemm_tc<<<dim3(1536 / 128, BN / 64), 256, GEMM_SMEM>>>(
        F16, wq, bqkv, nullptr, nullptr, qkv16, 1, 512, 1536);
    // attention -> fp16 O
    attn_tc<<<dim3(Nn / QT, Bb * Hh), 192, ATTN_SMEM>>>(qkv16, at16);
    // fenh = F + O @ Wout^T + bout -> fp16
    sgemm_tc<<<dim3(512 / 128, BN / 64), 256, GEMM_SMEM>>>(
        at16, wo, bout, F, nullptr, fe16, 0, 512, 512);
    // h = fenh @ w1^T + b1 -> fp32
    sgemm_tc<<<dim3(512 / 128, BN / 64), 256, GEMM_SMEM>>>(
        fe16, w1h, b1, nullptr, hbuf, nullptr, 0, 512, 512);
    // fused LN -> GELU -> comp -> outer -> topk -> write (4 rows/block)
    ln_outer_topk_kernel<<<BN / RPB, 512, FK_SMEM>>>(
        hbuf, lng, lnb, w2, b2, F, tmpl, out);
}

// round 15
// speedup vs baseline: 1.0826x; 1.0826x over previous
#include <cuda_runtime.h>
#include <cuda_fp16.h>
#include <math.h>

#define Bb   8
#define Nn   576
#define Dd   512
#define Mm   16
#define Hh   8
#define BN   (Bb*Nn)      // 4608
#define KTOP 51

typedef unsigned long long u64;
typedef unsigned int u32;

__device__ __forceinline__ u32 smem_u32(const void* p) {
    u32 a; asm("{ .reg .u64 t; cvta.to.shared.u64 t, %1; cvt.u32.u64 %0, t; }"
               : "=r"(a) : "l"(p));
    return a;
}

// ---- mma.sync helpers (fp16 in, fp32 acc) ----
__device__ __forceinline__ void ldsm4(u32* r, u32 addr) {
    asm volatile("ldmatrix.sync.aligned.m8n8.x4.shared.b16 {%0,%1,%2,%3}, [%4];"
                 : "=r"(r[0]), "=r"(r[1]), "=r"(r[2]), "=r"(r[3]) : "r"(addr));
}
__device__ __forceinline__ void ldsm4t(u32* r, u32 addr) {
    asm volatile("ldmatrix.sync.aligned.m8n8.x4.trans.shared.b16 {%0,%1,%2,%3}, [%4];"
                 : "=r"(r[0]), "=r"(r[1]), "=r"(r[2]), "=r"(r[3]) : "r"(addr));
}
__device__ __forceinline__ void mma16816(float* c, const u32* a, const u32* b) {
    asm volatile(
        "mma.sync.aligned.m16n8k16.row.col.f32.f16.f16.f32 "
        "{%0,%1,%2,%3}, {%4,%5,%6,%7}, {%8,%9}, {%0,%1,%2,%3};"
        : "+f"(c[0]), "+f"(c[1]), "+f"(c[2]), "+f"(c[3])
        : "r"(a[0]), "r"(a[1]), "r"(a[2]), "r"(a[3]), "r"(b[0]), "r"(b[1]));
}
__device__ __forceinline__ u32 h2pack(float x, float y) {
    __half2 h = __floats2half2_rn(x, y);
    return *(u32*)&h;
}

// ---- cp.async ----
__device__ __forceinline__ void cpa16(u32 saddr, const void* g) {
    asm volatile("cp.async.cg.shared.global [%0], [%1], 16;" :: "r"(saddr), "l"(g));
}
#define CP_COMMIT() asm volatile("cp.async.commit_group;" ::: "memory")
#define CP_WAIT0()  asm volatile("cp.async.wait_group 0;" ::: "memory")

// ---- scratch (fp16) ----
__device__ __half g_qkv[BN * 3 * Dd];   // qkv (Q pre-scaled 1/8)
__device__ __half g_F16[BN * Dd];
__device__ __half g_wq [3*Dd*Dd];
__device__ __half g_wo [Dd*Dd];
__device__ __half g_w1 [Dd*Dd];
__device__ __half g_at [BN * Dd];
__device__ __half g_fe [BN * Dd];
__device__ float  g_h  [BN * Dd];

// ============================================================
// One-launch fp32 -> fp16 convert over 4 tensors
// ============================================================
#define SEG0 589824
#define SEG1 (SEG0 + 196608)
#define SEG2 (SEG1 + 65536)
#define SEG3 (SEG2 + 65536)

__global__ __launch_bounds__(256) void cvt_all_kernel(
    const float* __restrict__ F,    const float* __restrict__ Wqkv,
    const float* __restrict__ Wout, const float* __restrict__ w1,
    __half* __restrict__ F16, __half* __restrict__ wq,
    __half* __restrict__ wo,  __half* __restrict__ w1h)
{
    int i = blockIdx.x * 256 + threadIdx.x;
    if (i >= SEG3) return;
    const float* src; __half* dst; int j;
    if (i < SEG0)      { src = F;    dst = F16; j = i; }
    else if (i < SEG1) { src = Wqkv; dst = wq;  j = i - SEG0; }
    else if (i < SEG2) { src = Wout; dst = wo;  j = i - SEG1; }
    else               { src = w1;   dst = w1h; j = i - SEG2; }
    float4 v = reinterpret_cast<const float4*>(src)[j];
    u32 h0 = h2pack(v.x, v.y), h1 = h2pack(v.z, v.w);
    reinterpret_cast<uint2*>(dst)[j] = make_uint2(h0, h1);
}

// ============================================================
// Tensor-core HGEMM v2 (kept from R14): 64x128 tile, 256 threads
// (8 warps 2x4), 2 CTAs/SM, cp.async 2-stage, K-chunk 32, 80B rows.
// ============================================================
#define GROWB 80
#define GA_BYTES (64 * GROWB)            // 5120
#define GB_OFF   GA_BYTES
#define GBUFSZ   (GA_BYTES + 128 * GROWB)  // 15360
#define GEMM_SMEM (2 * GBUFSZ)           // 30720

__global__ __launch_bounds__(256, 2) void sgemm_tc(
    const __half* __restrict__ A, const __half* __restrict__ B,
    const float* __restrict__ bias, const float* __restrict__ residual,
    float* __restrict__ C, __half* __restrict__ S16,
    int qsplit, int K, int N)
{
    extern __shared__ unsigned char smem[];
    const u32 sb = smem_u32(smem);

    const int tid = threadIdx.x;
    const int wid = tid >> 5, lid = tid & 31;
    const int rowBase = blockIdx.y * 64;
    const int colBase = blockIdx.x * 128;
    const int warp_m = (wid >> 2) * 32;
    const int warp_n = (wid & 3) * 32;

    const int lrow = tid >> 2;            // 0..63
    const int lc4  = tid & 3;
    const u32 soA  = (u32)lrow * GROWB + (u32)lc4 * 16;
    const u32 soB0 = GB_OFF + soA;
    const u32 soB1 = soB0 + 64u * GROWB;
    const char* pA  = (const char*)A + ((size_t)(rowBase + lrow) * K) * 2 + lc4 * 16;
    const char* pB0 = (const char*)B + ((size_t)(colBase + lrow) * K) * 2 + lc4 * 16;
    const char* pB1 = (const char*)B + ((size_t)(colBase + lrow + 64) * K) * 2 + lc4 * 16;

    const int a_row = warp_m + (lid & 15);
    const u32 a_kb  = (u32)(lid >> 4) * 16;
    const int b_n   = warp_n + (lid & 7) + ((lid >> 4) << 3);
    const u32 b_kb  = (u32)((lid >> 3) & 1) * 16;

    float acc[2][4][4];
    #pragma unroll
    for (int i = 0; i < 2; i++)
        #pragma unroll
        for (int j = 0; j < 4; j++)
            #pragma unroll
            for (int q = 0; q < 4; q++) acc[i][j][q] = 0.f;

    const int nChunk = K >> 5;
    {
        cpa16(sb + soA,  pA);
        cpa16(sb + soB0, pB0);
        cpa16(sb + soB1, pB1);
        CP_COMMIT();
    }

    for (int c = 0; c < nChunk; c++) {
        CP_WAIT0();
        __syncthreads();
        if (c + 1 < nChunk) {
            u32 d = sb + (u32)((c + 1) & 1) * GBUFSZ;
            size_t kb = (size_t)(c + 1) * 64;
            cpa16(d + soA,  pA  + kb);
            cpa16(d + soB0, pB0 + kb);
            cpa16(d + soB1, pB1 + kb);
            CP_COMMIT();
        }

        const u32 bufo = (u32)(c & 1) * GBUFSZ;
        #pragma unroll
        for (int ks = 0; ks < 2; ks++) {
            const u32 kso = (u32)ks * 32;
            u32 bfr[2][4];
            #pragma unroll
            for (int np = 0; np < 2; np++) {
                u32 ba = sb + bufo + GB_OFF + (u32)(b_n + np * 16) * GROWB + kso + b_kb;
                ldsm4(bfr[np], ba);
            }
            #pragma unroll
            for (int mt = 0; mt < 2; mt++) {
                u32 aa = sb + bufo + (u32)(a_row + mt * 16) * GROWB + kso + a_kb;
                u32 afr[4];
                ldsm4(afr, aa);
                #pragma unroll
                for (int nt = 0; nt < 4; nt++)
                    mma16816(acc[mt][nt], afr, &bfr[nt >> 1][(nt & 1) * 2]);
            }
        }
    }

    const int frow = lid >> 2;
    const int fcol = (lid & 3) * 2;
    #pragma unroll
    for (int mt = 0; mt < 2; mt++) {
        #pragma unroll
        for (int nt = 0; nt < 4; nt++) {
            int col = colBase + warp_n + nt * 8 + fcol;
            float2 bi = *reinterpret_cast<const float2*>(bias + col);
            #pragma unroll
            for (int half = 0; half < 2; half++) {
                int r = rowBase + warp_m + mt * 16 + frow + half * 8;
                float2 o;
                o.x = acc[mt][nt][half * 2 + 0] + bi.x;
                o.y = acc[mt][nt][half * 2 + 1] + bi.y;
                if (residual) {
                    float2 rv = *reinterpret_cast<const float2*>(residual + (size_t)r * N + col);
                    o.x += rv.x; o.y += rv.y;
                }
                if (C)
                    *reinterpret_cast<float2*>(C + (size_t)r * N + col) = o;
                if (S16) {
                    float sc = (qsplit && col < 512) ? 0.125f : 1.0f;
                    *reinterpret_cast<u32*>(S16 + (size_t)r * N + col) =
                        h2pack(o.x * sc, o.y * sc);
                }
            }
        }
    }
}

// ============================================================
// Tensor-core flash attention, plain fp16 (R13-passing, unchanged)
// ============================================================
#define ROWB 144
#define QT 96
#define KV_K 0
#define KV_V 9216
#define KVBUF 18432
#define AQ   (2 * KVBUF)
#define ATTN_SMEM (2 * KVBUF + 13824)

__global__ __launch_bounds__(192) void attn_tc(
    const __half* __restrict__ qkv, __half* __restrict__ oat)
{
    extern __shared__ unsigned char smem[];
    const u32 sb = smem_u32(smem);

    const int tid = threadIdx.x;
    const int wid = tid >> 5, lid = tid & 31;
    const int bh = blockIdx.y;
    const int b = bh >> 3, h = bh & 7;
    const int q0 = blockIdx.x * QT;

    const __half* qp = qkv + (size_t)(b * Nn + q0) * 1536 + h * 64;
    const __half* kp = qkv + (size_t)(b * Nn) * 1536 + 512  + h * 64;
    const __half* vp = qkv + (size_t)(b * Nn) * 1536 + 1024 + h * 64;

    for (int s = tid; s < 512; s += 192) {
        int row = s >> 3, c8 = s & 7;
        size_t go = (size_t)row * 1536 + c8 * 8;
        u32 so = sb + (u32)row * ROWB + (u32)c8 * 16;
        cpa16(so + KV_K, kp + go);
        cpa16(so + KV_V, vp + go);
    }
    #pragma unroll
    for (int it = 0; it < 4; it++) {
        int s = tid + it * 192;
        int row = s >> 3, c8 = s & 7;
        size_t go = (size_t)row * 1536 + c8 * 8;
        cpa16(sb + AQ + (u32)row * ROWB + (u32)c8 * 16, qp + go);
    }
    CP_COMMIT();
    CP_WAIT0();
    __syncthreads();

    u32 qf[4][4];
    {
        const int a_row = (wid << 4) + (lid & 15);
        const u32 a_kb = (u32)(lid >> 4) * 16;
        #pragma unroll
        for (int kt = 0; kt < 4; kt++)
            ldsm4(qf[kt], sb + AQ + (u32)a_row * ROWB + (u32)kt * 32 + a_kb);
    }

    float m_lo = -1e30f, m_hi = -1e30f, l_lo = 0.f, l_hi = 0.f;
    float oacc[8][4];
    #pragma unroll
    for (int j = 0; j < 8; j++)
        #pragma unroll
        for (int q = 0; q < 4; q++) oacc[j][q] = 0.f;

    const int kb_row = (lid & 7) + ((lid >> 4) << 3);
    const u32 kb_kb  = (u32)((lid >> 3) & 1) * 16;
    const int vb_key = (lid & 7) + (((lid >> 3) & 1) << 3);
    const u32 vb_db  = (u32)(lid >> 4) * 16;

    const int nChunk = Nn / 64;
    for (int c = 0; c < nChunk; c++) {
        if (c + 1 < nChunk) {
            const u32 nb = sb + (u32)((c + 1) & 1) * KVBUF;
            const int kc1 = (c + 1) * 64;
            for (int s = tid; s < 512; s += 192) {
                int row = s >> 3, c8 = s & 7;
                size_t go = (size_t)(kc1 + row) * 1536 + c8 * 8;
                u32 so = nb + (u32)row * ROWB + (u32)c8 * 16;
                cpa16(so + KV_K, kp + go);
                cpa16(so + KV_V, vp + go);
            }
        }
        CP_COMMIT();

        const u32 bufb = sb + (u32)(c & 1) * KVBUF;

        float sacc[8][4];
        #pragma unroll
        for (int j = 0; j < 8; j++)
            #pragma unroll
            for (int q = 0; q < 4; q++) sacc[j][q] = 0.f;

        #pragma unroll
        for (int kt = 0; kt < 4; kt++) {
            #pragma unroll
            for (int ng = 0; ng < 4; ng++) {
                u32 ka = bufb + KV_K + (u32)(ng * 16 + kb_row) * ROWB + (u32)kt * 32 + kb_kb;
                u32 kf[4];
                ldsm4(kf, ka);
                mma16816(sacc[2 * ng + 0], qf[kt], &kf[0]);
                mma16816(sacc[2 * ng + 1], qf[kt], &kf[2]);
            }
        }

        float mx_lo = -1e30f, mx_hi = -1e30f;
        #pragma unroll
        for (int j = 0; j < 8; j++) {
            mx_lo = fmaxf(mx_lo, fmaxf(sacc[j][0], sacc[j][1]));
            mx_hi = fmaxf(mx_hi, fmaxf(sacc[j][2], sacc[j][3]));
        }
        #pragma unroll
        for (int o = 1; o <= 2; o <<= 1) {
            mx_lo = fmaxf(mx_lo, __shfl_xor_sync(0xffffffffu, mx_lo, o));
            mx_hi = fmaxf(mx_hi, __shfl_xor_sync(0xffffffffu, mx_hi, o));
        }
        float mn_lo = fmaxf(m_lo, mx_lo), mn_hi = fmaxf(m_hi, mx_hi);
        float corr_lo = __expf(m_lo - mn_lo), corr_hi = __expf(m_hi - mn_hi);
        float rs_lo = 0.f, rs_hi = 0.f;
        #pragma unroll
        for (int j = 0; j < 8; j++) {
            sacc[j][0] = __expf(sacc[j][0] - mn_lo);
            sacc[j][1] = __expf(sacc[j][1] - mn_lo);
            sacc[j][2] = __expf(sacc[j][2] - mn_hi);
            sacc[j][3] = __expf(sacc[j][3] - mn_hi);
            rs_lo += sacc[j][0] + sacc[j][1];
            rs_hi += sacc[j][2] + sacc[j][3];
        }
        #pragma unroll
        for (int o = 1; o <= 2; o <<= 1) {
            rs_lo += __shfl_xor_sync(0xffffffffu, rs_lo, o);
            rs_hi += __shfl_xor_sync(0xffffffffu, rs_hi, o);
        }
        l_lo = l_lo * corr_lo + rs_lo;
        l_hi = l_hi * corr_hi + rs_hi;
        m_lo = mn_lo; m_hi = mn_hi;
        #pragma unroll
        for (int j = 0; j < 8; j++) {
            oacc[j][0] *= corr_lo; oacc[j][1] *= corr_lo;
            oacc[j][2] *= corr_hi; oacc[j][3] *= corr_hi;
        }

        #pragma unroll
        for (int kt = 0; kt < 4; kt++) {
            const int j0 = 2 * kt, j1 = 2 * kt + 1;
            u32 ap[4];
            ap[0] = h2pack(sacc[j0][0], sacc[j0][1]);
            ap[1] = h2pack(sacc[j0][2], sacc[j0][3]);
            ap[2] = h2pack(sacc[j1][0], sacc[j1][1]);
            ap[3] = h2pack(sacc[j1][2], sacc[j1][3]);
            #pragma unroll
            for (int ng = 0; ng < 4; ng++) {
                u32 va = bufb + KV_V + (u32)(kt * 16 + vb_key) * ROWB + (u32)ng * 32 + vb_db;
                u32 vf[4];
                ldsm4t(vf, va);
                mma16816(oacc[2 * ng + 0], ap, &vf[0]);
                mma16816(oacc[2 * ng + 1], ap, &vf[2]);
            }
        }

        CP_WAIT0();
        __syncthreads();
    }

    const float inv_lo = 1.f / l_lo, inv_hi = 1.f / l_hi;
    const int r_lo = q0 + (wid << 4) + (lid >> 2);
    const int cb = h * 64 + (lid & 3) * 2;
    #pragma unroll
    for (int j = 0; j < 8; j++) {
        int col = cb + j * 8;
        *reinterpret_cast<u32*>(oat + (size_t)(b * Nn + r_lo) * Dd + col) =
            h2pack(oacc[j][0] * inv_lo, oacc[j][1] * inv_lo);
        *reinterpret_cast<u32*>(oat + (size_t)(b * Nn + r_lo + 8) * Dd + col) =
            h2pack(oacc[j][2] * inv_hi, oacc[j][3] * inv_hi);
    }
}

// ============================================================
// FUSED: LayerNorm -> GELU -> comp -> outer -> top-51 -> write
// (R13-passing form: 1 row/block, static smem, global w2/tmpl)
// ============================================================
__global__ __launch_bounds__(512) void ln_outer_topk_kernel(
    const float* __restrict__ hsrc,
    const float* __restrict__ ln_g, const float* __restrict__ ln_b,
    const float* __restrict__ w2,  const float* __restrict__ b2,
    const float* __restrict__ F, const float* __restrict__ templates,
    float* __restrict__ out)
{
    __shared__ float s[512];
    __shared__ float Frow[512];
    __shared__ float red[32];
    __shared__ float cs[16];
    __shared__ float Qout[512 * 17];

    const int row = blockIdx.x;
    const int tid = threadIdx.x;
    const int m = tid >> 5, lid = tid & 31;

    float x = hsrc[(size_t)row * 512 + tid];
    s[tid] = x;
    Frow[tid] = F[(size_t)row * 512 + tid];

    float sum = x, sq = x * x;
    #pragma unroll
    for (int o = 16; o >= 1; o >>= 1) {
        sum += __shfl_xor_sync(0xffffffffu, sum, o);
        sq  += __shfl_xor_sync(0xffffffffu, sq,  o);
    }
    if (lid == 0) { red[m] = sum; red[m + 16] = sq; }
    __syncthreads();
    if (tid == 0) {
        float S = 0.f, Q = 0.f;
        #pragma unroll
        for (int i = 0; i < 16; i++) { S += red[i]; Q += red[i + 16]; }
        red[0] = S * (1.f / 512.f);
        red[16] = Q * (1.f / 512.f);
    }
    __syncthreads();
    const float mean = red[0];
    const float rstd = rsqrtf(red[16] - mean * mean + 1e-5f);

    float g = (x - mean) * rstd * ln_g[tid] + ln_b[tid];
    g = 0.5f * g * (1.f + erff(g * 0.70710678118f));
    __syncthreads();
    s[tid] = g;
    __syncthreads();

    {
        float p = 0.f;
        const float* wrow = w2 + m * 512;
        #pragma unroll
        for (int i = 0; i < 16; i++) {
            int e = lid + 32 * i;
            p += s[e] * wrow[e];
        }
        #pragma unroll
        for (int o = 16; o >= 1; o >>= 1)
            p += __shfl_xor_sync(0xffffffffu, p, o);
        if (lid == 0) cs[m] = p + b2[m];
    }
    __syncthreads();

    const float c = cs[m];
    float    qv[16];
    unsigned key[16];
    unsigned mx = 0;
    #pragma unroll
    for (int i = 0; i < 16; i++) {
        int d = lid + 32 * i;
        float q = Frow[d] * templates[m * 512 + d] * c;
        qv[i]  = q;
        key[i] = __float_as_uint(fabsf(q));
        mx = max(mx, key[i]);
    }
    #pragma unroll
    for (int o = 16; o >= 1; o >>= 1)
        mx = max(mx, __shfl_xor_sync(0xffffffffu, mx, o));

    unsigned prefix = 0;
    int bit = 31 - __clz(mx | 1u);
    for (; bit >= 0; bit--) {
        unsigned test = prefix | (1u << bit);
        int cnt = 0;
        #pragma unroll
        for (int i = 0; i < 16; i++) cnt += (key[i] >= test);
        cnt = __reduce_add_sync(0xffffffffu, cnt);
        if (cnt >= KTOP) {
            prefix = test;
            if (cnt == KTOP) break;
        }
    }

    #pragma unroll
    for (int i = 0; i < 16; i++) {
        int d = lid + 32 * i;
        Qout[d * 17 + m] = (key[i] >= prefix) ? qv[i] : 0.f;
    }
    __syncthreads();

    float* ob = out + (size_t)row * (512 * 16);
    #pragma unroll
    for (int i = 0; i < 16; i++) {
        int e = tid + 512 * i;
        ob[e] = Qout[(e >> 4) * 17 + (e & 15)];
    }
}

// ============================================================
extern "C" void kernel_launch(void* const* d_in, const int* in_sizes, int n_in,
                              void* d_out, int out_size) {
    const float* F    = (const float*)d_in[0];
    const float* Wqkv = (const float*)d_in[1];
    const float* bqkv = (const float*)d_in[2];
    const float* Wout = (const float*)d_in[3];
    const float* bout = (const float*)d_in[4];
    const float* w1   = (const float*)d_in[5];
    const float* b1   = (const float*)d_in[6];
    const float* lng  = (const float*)d_in[7];
    const float* lnb  = (const float*)d_in[8];
    const float* w2   = (const float*)d_in[9];
    const float* b2   = (const float*)d_in[10];
    const float* tmpl = (const float*)d_in[11];
    float* out = (float*)d_out;

    __half *qkv16, *F16, *wq, *wo, *w1h, *at16, *fe16;
    float *hbuf;
    cudaGetSymbolAddress((void**)&qkv16, g_qkv);
    cudaGetSymbolAddress((void**)&F16,   g_F16);
    cudaGetSymbolAddress((void**)&wq,    g_wq);
    cudaGetSymbolAddress((void**)&wo,    g_wo);
    cudaGetSymbolAddress((void**)&w1h,   g_w1);
    cudaGetSymbolAddress((void**)&at16,  g_at);
    cudaGetSymbolAddress((void**)&fe16,  g_fe);
    cudaGetSymbolAddress((void**)&hbuf,  g_h);

    cudaFuncSetAttribute(sgemm_tc, cudaFuncAttributeMaxDynamicSharedMemorySize,
                         GEMM_SMEM);
    cudaFuncSetAttribute(attn_tc, cudaFuncAttributeMaxDynamicSharedMemorySize,
                         ATTN_SMEM);

    cvt_all_kernel<<<(SEG3 + 255) / 256, 256>>>(F, Wqkv, Wout, w1, F16, wq, wo, w1h);

    // qkv = F @ Wqkv^T + bqkv -> fp16 (Q scaled 1/8)
    sgemm_tc<<<dim3(1536 / 128, BN / 64), 256, GEMM_SMEM>>>(
        F16, wq, bqkv, nullptr, nullptr, qkv16, 1, 512, 1536);
    // attention -> fp16 O
    attn_tc<<<dim3(Nn / QT, Bb * Hh), 192, ATTN_SMEM>>>(qkv16, at16);
    // fenh = F + O @ Wout^T + bout -> fp16
    sgemm_tc<<<dim3(512 / 128, BN / 64), 256, GEMM_SMEM>>>(
        at16, wo, bout, F, nullptr, fe16, 0, 512, 512);
    // h = fenh @ w1^T + b1 -> fp32
    sgemm_tc<<<dim3(512 / 128, BN / 64), 256, GEMM_SMEM>>>(
        fe16, w1h, b1, nullptr, hbuf, nullptr, 0, 512, 512);
    // fused LN -> GELU -> comp -> outer -> topk -> write (1 row/block)
    ln_outer_topk_kernel<<<BN, 512>>>(hbuf, lng, lnb, w2, b2, F, tmpl, out);
}

// round 16
// speedup vs baseline: 1.0927x; 1.0093x over previous
#include <cuda_runtime.h>
#include <cuda_fp16.h>
#include <math.h>

#define Bb   8
#define Nn   576
#define Dd   512
#define Mm   16
#define Hh   8
#define BN   (Bb*Nn)      // 4608
#define KTOP 51

typedef unsigned long long u64;
typedef unsigned int u32;

__device__ __forceinline__ u32 smem_u32(const void* p) {
    u32 a; asm("{ .reg .u64 t; cvta.to.shared.u64 t, %1; cvt.u32.u64 %0, t; }"
               : "=r"(a) : "l"(p));
    return a;
}

// ---- mma.sync helpers (fp16 in, fp32 acc) ----
__device__ __forceinline__ void ldsm4(u32* r, u32 addr) {
    asm volatile("ldmatrix.sync.aligned.m8n8.x4.shared.b16 {%0,%1,%2,%3}, [%4];"
                 : "=r"(r[0]), "=r"(r[1]), "=r"(r[2]), "=r"(r[3]) : "r"(addr));
}
__device__ __forceinline__ void ldsm4t(u32* r, u32 addr) {
    asm volatile("ldmatrix.sync.aligned.m8n8.x4.trans.shared.b16 {%0,%1,%2,%3}, [%4];"
                 : "=r"(r[0]), "=r"(r[1]), "=r"(r[2]), "=r"(r[3]) : "r"(addr));
}
__device__ __forceinline__ void mma16816(float* c, const u32* a, const u32* b) {
    asm volatile(
        "mma.sync.aligned.m16n8k16.row.col.f32.f16.f16.f32 "
        "{%0,%1,%2,%3}, {%4,%5,%6,%7}, {%8,%9}, {%0,%1,%2,%3};"
        : "+f"(c[0]), "+f"(c[1]), "+f"(c[2]), "+f"(c[3])
        : "r"(a[0]), "r"(a[1]), "r"(a[2]), "r"(a[3]), "r"(b[0]), "r"(b[1]));
}
__device__ __forceinline__ u32 h2pack(float x, float y) {
    __half2 h = __floats2half2_rn(x, y);
    return *(u32*)&h;
}
// packed half2 exp2: one MUFU op, two exps, result is a ready PV fragment
__device__ __forceinline__ u32 ex2h2(float x, float y) {
    u32 r = h2pack(x, y);
    asm("ex2.approx.f16x2 %0, %0;" : "+r"(r));
    return r;
}

// ---- cp.async ----
__device__ __forceinline__ void cpa16(u32 saddr, const void* g) {
    asm volatile("cp.async.cg.shared.global [%0], [%1], 16;" :: "r"(saddr), "l"(g));
}
#define CP_COMMIT() asm volatile("cp.async.commit_group;" ::: "memory")
#define CP_WAIT0()  asm volatile("cp.async.wait_group 0;" ::: "memory")

// ---- scratch (fp16) ----
__device__ __half g_qkv[BN * 3 * Dd];   // qkv (Q pre-scaled 1/8)
__device__ __half g_F16[BN * Dd];
__device__ __half g_wq [3*Dd*Dd];
__device__ __half g_wo [Dd*Dd];
__device__ __half g_w1 [Dd*Dd];
__device__ __half g_at [BN * Dd];
__device__ __half g_fe [BN * Dd];
__device__ float  g_h  [BN * Dd];

// ============================================================
// One-launch fp32 -> fp16 convert over 4 tensors
// ============================================================
#define SEG0 589824
#define SEG1 (SEG0 + 196608)
#define SEG2 (SEG1 + 65536)
#define SEG3 (SEG2 + 65536)

__global__ __launch_bounds__(256) void cvt_all_kernel(
    const float* __restrict__ F,    const float* __restrict__ Wqkv,
    const float* __restrict__ Wout, const float* __restrict__ w1,
    __half* __restrict__ F16, __half* __restrict__ wq,
    __half* __restrict__ wo,  __half* __restrict__ w1h)
{
    int i = blockIdx.x * 256 + threadIdx.x;
    if (i >= SEG3) return;
    const float* src; __half* dst; int j;
    if (i < SEG0)      { src = F;    dst = F16; j = i; }
    else if (i < SEG1) { src = Wqkv; dst = wq;  j = i - SEG0; }
    else if (i < SEG2) { src = Wout; dst = wo;  j = i - SEG1; }
    else               { src = w1;   dst = w1h; j = i - SEG2; }
    float4 v = reinterpret_cast<const float4*>(src)[j];
    u32 h0 = h2pack(v.x, v.y), h1 = h2pack(v.z, v.w);
    reinterpret_cast<uint2*>(dst)[j] = make_uint2(h0, h1);
}

// ============================================================
// Tensor-core HGEMM (R15-passing): 64x128 tile, 256 threads,
// 2 CTAs/SM, cp.async 2-stage, K-chunk 32, 80B rows.
// ============================================================
#define GROWB 80
#define GA_BYTES (64 * GROWB)
#define GB_OFF   GA_BYTES
#define GBUFSZ   (GA_BYTES + 128 * GROWB)
#define GEMM_SMEM (2 * GBUFSZ)

__global__ __launch_bounds__(256, 2) void sgemm_tc(
    const __half* __restrict__ A, const __half* __restrict__ B,
    const float* __restrict__ bias, const float* __restrict__ residual,
    float* __restrict__ C, __half* __restrict__ S16,
    int qsplit, int K, int N)
{
    extern __shared__ unsigned char smem[];
    const u32 sb = smem_u32(smem);

    const int tid = threadIdx.x;
    const int wid = tid >> 5, lid = tid & 31;
    const int rowBase = blockIdx.y * 64;
    const int colBase = blockIdx.x * 128;
    const int warp_m = (wid >> 2) * 32;
    const int warp_n = (wid & 3) * 32;

    const int lrow = tid >> 2;
    const int lc4  = tid & 3;
    const u32 soA  = (u32)lrow * GROWB + (u32)lc4 * 16;
    const u32 soB0 = GB_OFF + soA;
    const u32 soB1 = soB0 + 64u * GROWB;
    const char* pA  = (const char*)A + ((size_t)(rowBase + lrow) * K) * 2 + lc4 * 16;
    const char* pB0 = (const char*)B + ((size_t)(colBase + lrow) * K) * 2 + lc4 * 16;
    const char* pB1 = (const char*)B + ((size_t)(colBase + lrow + 64) * K) * 2 + lc4 * 16;

    const int a_row = warp_m + (lid & 15);
    const u32 a_kb  = (u32)(lid >> 4) * 16;
    const int b_n   = warp_n + (lid & 7) + ((lid >> 4) << 3);
    const u32 b_kb  = (u32)((lid >> 3) & 1) * 16;

    float acc[2][4][4];
    #pragma unroll
    for (int i = 0; i < 2; i++)
        #pragma unroll
        for (int j = 0; j < 4; j++)
            #pragma unroll
            for (int q = 0; q < 4; q++) acc[i][j][q] = 0.f;

    const int nChunk = K >> 5;
    {
        cpa16(sb + soA,  pA);
        cpa16(sb + soB0, pB0);
        cpa16(sb + soB1, pB1);
        CP_COMMIT();
    }

    for (int c = 0; c < nChunk; c++) {
        CP_WAIT0();
        __syncthreads();
        if (c + 1 < nChunk) {
            u32 d = sb + (u32)((c + 1) & 1) * GBUFSZ;
            size_t kb = (size_t)(c + 1) * 64;
            cpa16(d + soA,  pA  + kb);
            cpa16(d + soB0, pB0 + kb);
            cpa16(d + soB1, pB1 + kb);
            CP_COMMIT();
        }

        const u32 bufo = (u32)(c & 1) * GBUFSZ;
        #pragma unroll
        for (int ks = 0; ks < 2; ks++) {
            const u32 kso = (u32)ks * 32;
            u32 bfr[2][4];
            #pragma unroll
            for (int np = 0; np < 2; np++) {
                u32 ba = sb + bufo + GB_OFF + (u32)(b_n + np * 16) * GROWB + kso + b_kb;
                ldsm4(bfr[np], ba);
            }
            #pragma unroll
            for (int mt = 0; mt < 2; mt++) {
                u32 aa = sb + bufo + (u32)(a_row + mt * 16) * GROWB + kso + a_kb;
                u32 afr[4];
                ldsm4(afr, aa);
                #pragma unroll
                for (int nt = 0; nt < 4; nt++)
                    mma16816(acc[mt][nt], afr, &bfr[nt >> 1][(nt & 1) * 2]);
            }
        }
    }

    const int frow = lid >> 2;
    const int fcol = (lid & 3) * 2;
    #pragma unroll
    for (int mt = 0; mt < 2; mt++) {
        #pragma unroll
        for (int nt = 0; nt < 4; nt++) {
            int col = colBase + warp_n + nt * 8 + fcol;
            float2 bi = *reinterpret_cast<const float2*>(bias + col);
            #pragma unroll
            for (int half = 0; half < 2; half++) {
                int r = rowBase + warp_m + mt * 16 + frow + half * 8;
                float2 o;
                o.x = acc[mt][nt][half * 2 + 0] + bi.x;
                o.y = acc[mt][nt][half * 2 + 1] + bi.y;
                if (residual) {
                    float2 rv = *reinterpret_cast<const float2*>(residual + (size_t)r * N + col);
                    o.x += rv.x; o.y += rv.y;
                }
                if (C)
                    *reinterpret_cast<float2*>(C + (size_t)r * N + col) = o;
                if (S16) {
                    float sc = (qsplit && col < 512) ? 0.125f : 1.0f;
                    *reinterpret_cast<u32*>(S16 + (size_t)r * N + col) =
                        h2pack(o.x * sc, o.y * sc);
                }
            }
        }
    }
}

// ============================================================
// Tensor-core flash attention, fp16 + f16x2 packed exp.
// q-tile 96, 6 warps, cp.async double-buffered K/V.
// ============================================================
#define ROWB 144
#define QT 96
#define KV_K 0
#define KV_V 9216
#define KVBUF 18432
#define AQ   (2 * KVBUF)
#define ATTN_SMEM (2 * KVBUF + 13824)

__global__ __launch_bounds__(192) void attn_tc(
    const __half* __restrict__ qkv, __half* __restrict__ oat)
{
    extern __shared__ unsigned char smem[];
    const u32 sb = smem_u32(smem);

    const int tid = threadIdx.x;
    const int wid = tid >> 5, lid = tid & 31;
    const int bh = blockIdx.y;
    const int b = bh >> 3, h = bh & 7;
    const int q0 = blockIdx.x * QT;
    const float L2E = 1.44269504f;

    const __half* qp = qkv + (size_t)(b * Nn + q0) * 1536 + h * 64;
    const __half* kp = qkv + (size_t)(b * Nn) * 1536 + 512  + h * 64;
    const __half* vp = qkv + (size_t)(b * Nn) * 1536 + 1024 + h * 64;

    for (int s = tid; s < 512; s += 192) {
        int row = s >> 3, c8 = s & 7;
        size_t go = (size_t)row * 1536 + c8 * 8;
        u32 so = sb + (u32)row * ROWB + (u32)c8 * 16;
        cpa16(so + KV_K, kp + go);
        cpa16(so + KV_V, vp + go);
    }
    #pragma unroll
    for (int it = 0; it < 4; it++) {
        int s = tid + it * 192;
        int row = s >> 3, c8 = s & 7;
        size_t go = (size_t)row * 1536 + c8 * 8;
        cpa16(sb + AQ + (u32)row * ROWB + (u32)c8 * 16, qp + go);
    }
    CP_COMMIT();
    CP_WAIT0();
    __syncthreads();

    u32 qf[4][4];
    {
        const int a_row = (wid << 4) + (lid & 15);
        const u32 a_kb = (u32)(lid >> 4) * 16;
        #pragma unroll
        for (int kt = 0; kt < 4; kt++)
            ldsm4(qf[kt], sb + AQ + (u32)a_row * ROWB + (u32)kt * 32 + a_kb);
    }

    float m_lo = -1e30f, m_hi = -1e30f, l_lo = 0.f, l_hi = 0.f;
    float oacc[8][4];
    #pragma unroll
    for (int j = 0; j < 8; j++)
        #pragma unroll
        for (int q = 0; q < 4; q++) oacc[j][q] = 0.f;

    const int kb_row = (lid & 7) + ((lid >> 4) << 3);
    const u32 kb_kb  = (u32)((lid >> 3) & 1) * 16;
    const int vb_key = (lid & 7) + (((lid >> 3) & 1) << 3);
    const u32 vb_db  = (u32)(lid >> 4) * 16;

    const int nChunk = Nn / 64;
    for (int c = 0; c < nChunk; c++) {
        if (c + 1 < nChunk) {
            const u32 nb = sb + (u32)((c + 1) & 1) * KVBUF;
            const int kc1 = (c + 1) * 64;
            for (int s = tid; s < 512; s += 192) {
                int row = s >> 3, c8 = s & 7;
                size_t go = (size_t)(kc1 + row) * 1536 + c8 * 8;
                u32 so = nb + (u32)row * ROWB + (u32)c8 * 16;
                cpa16(so + KV_K, kp + go);
                cpa16(so + KV_V, vp + go);
            }
        }
        CP_COMMIT();

        const u32 bufb = sb + (u32)(c & 1) * KVBUF;

        // ---- S = Q K^T ----
        float sacc[8][4];
        #pragma unroll
        for (int j = 0; j < 8; j++)
            #pragma unroll
            for (int q = 0; q < 4; q++) sacc[j][q] = 0.f;

        #pragma unroll
        for (int kt = 0; kt < 4; kt++) {
            #pragma unroll
            for (int ng = 0; ng < 4; ng++) {
                u32 ka = bufb + KV_K + (u32)(ng * 16 + kb_row) * ROWB + (u32)kt * 32 + kb_kb;
                u32 kf[4];
                ldsm4(kf, ka);
                mma16816(sacc[2 * ng + 0], qf[kt], &kf[0]);
                mma16816(sacc[2 * ng + 1], qf[kt], &kf[2]);
            }
        }

        // ---- online softmax: f16x2 packed exp2 ----
        float mx_lo = -1e30f, mx_hi = -1e30f;
        #pragma unroll
        for (int j = 0; j < 8; j++) {
            mx_lo = fmaxf(mx_lo, fmaxf(sacc[j][0], sacc[j][1]));
            mx_hi = fmaxf(mx_hi, fmaxf(sacc[j][2], sacc[j][3]));
        }
        #pragma unroll
        for (int o = 1; o <= 2; o <<= 1) {
            mx_lo = fmaxf(mx_lo, __shfl_xor_sync(0xffffffffu, mx_lo, o));
            mx_hi = fmaxf(mx_hi, __shfl_xor_sync(0xffffffffu, mx_hi, o));
        }
        float mn_lo = fmaxf(m_lo, mx_lo), mn_hi = fmaxf(m_hi, mx_hi);
        float corr_lo = __expf(m_lo - mn_lo), corr_hi = __expf(m_hi - mn_hi);

        u32 pex[8][2];
        float rs_lo = 0.f, rs_hi = 0.f;
        #pragma unroll
        for (int j = 0; j < 8; j++) {
            pex[j][0] = ex2h2((sacc[j][0] - mn_lo) * L2E, (sacc[j][1] - mn_lo) * L2E);
            pex[j][1] = ex2h2((sacc[j][2] - mn_hi) * L2E, (sacc[j][3] - mn_hi) * L2E);
            float2 f0 = __half22float2(*reinterpret_cast<__half2*>(&pex[j][0]));
            float2 f1 = __half22float2(*reinterpret_cast<__half2*>(&pex[j][1]));
            rs_lo += f0.x + f0.y;
            rs_hi += f1.x + f1.y;
        }
        #pragma unroll
        for (int o = 1; o <= 2; o <<= 1) {
            rs_lo += __shfl_xor_sync(0xffffffffu, rs_lo, o);
            rs_hi += __shfl_xor_sync(0xffffffffu, rs_hi, o);
        }
        l_lo = l_lo * corr_lo + rs_lo;
        l_hi = l_hi * corr_hi + rs_hi;
        m_lo = mn_lo; m_hi = mn_hi;
        #pragma unroll
        for (int j = 0; j < 8; j++) {
            oacc[j][0] *= corr_lo; oacc[j][1] *= corr_lo;
            oacc[j][2] *= corr_hi; oacc[j][3] *= corr_hi;
        }

        // ---- O += P V (P fragments come straight from ex2h2) ----
        #pragma unroll
        for (int kt = 0; kt < 4; kt++) {
            const int j0 = 2 * kt, j1 = 2 * kt + 1;
            u32 ap[4];
            ap[0] = pex[j0][0];
            ap[1] = pex[j0][1];
            ap[2] = pex[j1][0];
            ap[3] = pex[j1][1];
            #pragma unroll
            for (int ng = 0; ng < 4; ng++) {
                u32 va = bufb + KV_V + (u32)(kt * 16 + vb_key) * ROWB + (u32)ng * 32 + vb_db;
                u32 vf[4];
                ldsm4t(vf, va);
                mma16816(oacc[2 * ng + 0], ap, &vf[0]);
                mma16816(oacc[2 * ng + 1], ap, &vf[2]);
            }
        }

        CP_WAIT0();
        __syncthreads();
    }

    const float inv_lo = 1.f / l_lo, inv_hi = 1.f / l_hi;
    const int r_lo = q0 + (wid << 4) + (lid >> 2);
    const int cb = h * 64 + (lid & 3) * 2;
    #pragma unroll
    for (int j = 0; j < 8; j++) {
        int col = cb + j * 8;
        *reinterpret_cast<u32*>(oat + (size_t)(b * Nn + r_lo) * Dd + col) =
            h2pack(oacc[j][0] * inv_lo, oacc[j][1] * inv_lo);
        *reinterpret_cast<u32*>(oat + (size_t)(b * Nn + r_lo + 8) * Dd + col) =
            h2pack(oacc[j][2] * inv_hi, oacc[j][3] * inv_hi);
    }
}

// ============================================================
// FUSED: LayerNorm -> GELU -> comp -> outer -> top-51 -> write
// (R15-passing, unchanged)
// ============================================================
__global__ __launch_bounds__(512) void ln_outer_topk_kernel(
    const float* __restrict__ hsrc,
    const float* __restrict__ ln_g, const float* __restrict__ ln_b,
    const float* __restrict__ w2,  const float* __restrict__ b2,
    const float* __restrict__ F, const float* __restrict__ templates,
    float* __restrict__ out)
{
    __shared__ float s[512];
    __shared__ float Frow[512];
    __shared__ float red[32];
    __shared__ float cs[16];
    __shared__ float Qout[512 * 17];

    const int row = blockIdx.x;
    const int tid = threadIdx.x;
    const int m = tid >> 5, lid = tid & 31;

    float x = hsrc[(size_t)row * 512 + tid];
    s[tid] = x;
    Frow[tid] = F[(size_t)row * 512 + tid];

    float sum = x, sq = x * x;
    #pragma unroll
    for (int o = 16; o >= 1; o >>= 1) {
        sum += __shfl_xor_sync(0xffffffffu, sum, o);
        sq  += __shfl_xor_sync(0xffffffffu, sq,  o);
    }
    if (lid == 0) { red[m] = sum; red[m + 16] = sq; }
    __syncthreads();
    if (tid == 0) {
        float S = 0.f, Q = 0.f;
        #pragma unroll
        for (int i = 0; i < 16; i++) { S += red[i]; Q += red[i + 16]; }
        red[0] = S * (1.f / 512.f);
        red[16] = Q * (1.f / 512.f);
    }
    __syncthreads();
    const float mean = red[0];
    const float rstd = rsqrtf(red[16] - mean * mean + 1e-5f);

    float g = (x - mean) * rstd * ln_g[tid] + ln_b[tid];
    g = 0.5f * g * (1.f + erff(g * 0.70710678118f));
    __syncthreads();
    s[tid] = g;
    __syncthreads();

    {
        float p = 0.f;
        const float* wrow = w2 + m * 512;
        #pragma unroll
        for (int i = 0; i < 16; i++) {
            int e = lid + 32 * i;
            p += s[e] * wrow[e];
        }
        #pragma unroll
        for (int o = 16; o >= 1; o >>= 1)
            p += __shfl_xor_sync(0xffffffffu, p, o);
        if (lid == 0) cs[m] = p + b2[m];
    }
    __syncthreads();

    const float c = cs[m];
    float    qv[16];
    unsigned key[16];
    unsigned mx = 0;
    #pragma unroll
    for (int i = 0; i < 16; i++) {
        int d = lid + 32 * i;
        float q = Frow[d] * templates[m * 512 + d] * c;
        qv[i]  = q;
        key[i] = __float_as_uint(fabsf(q));
        mx = max(mx, key[i]);
    }
    #pragma unroll
    for (int o = 16; o >= 1; o >>= 1)
        mx = max(mx, __shfl_xor_sync(0xffffffffu, mx, o));

    unsigned prefix = 0;
    int bit = 31 - __clz(mx | 1u);
    for (; bit >= 0; bit--) {
        unsigned test = prefix | (1u << bit);
        int cnt = 0;
        #pragma unroll
        for (int i = 0; i < 16; i++) cnt += (key[i] >= test);
        cnt = __reduce_add_sync(0xffffffffu, cnt);
        if (cnt >= KTOP) {
            prefix = test;
            if (cnt == KTOP) break;
        }
    }

    #pragma unroll
    for (int i = 0; i < 16; i++) {
        int d = lid + 32 * i;
        Qout[d * 17 + m] = (key[i] >= prefix) ? qv[i] : 0.f;
    }
    __syncthreads();

    float* ob = out + (size_t)row * (512 * 16);
    #pragma unroll
    for (int i = 0; i < 16; i++) {
        int e = tid + 512 * i;
        ob[e] = Qout[(e >> 4) * 17 + (e & 15)];
    }
}

// ============================================================
extern "C" void kernel_launch(void* const* d_in, const int* in_sizes, int n_in,
                              void* d_out, int out_size) {
    const float* F    = (const float*)d_in[0];
    const float* Wqkv = (const float*)d_in[1];
    const float* bqkv = (const float*)d_in[2];
    const float* Wout = (const float*)d_in[3];
    const float* bout = (const float*)d_in[4];
    const float* w1   = (const float*)d_in[5];
    const float* b1   = (const float*)d_in[6];
    const float* lng  = (const float*)d_in[7];
    const float* lnb  = (const float*)d_in[8];
    const float* w2   = (const float*)d_in[9];
    const float* b2   = (const float*)d_in[10];
    const float* tmpl = (const float*)d_in[11];
    float* out = (float*)d_out;

    __half *qkv16, *F16, *wq, *wo, *w1h, *at16, *fe16;
    float *hbuf;
    cudaGetSymbolAddress((void**)&qkv16, g_qkv);
    cudaGetSymbolAddress((void**)&F16,   g_F16);
    cudaGetSymbolAddress((void**)&wq,    g_wq);
    cudaGetSymbolAddress((void**)&wo,    g_wo);
    cudaGetSymbolAddress((void**)&w1h,   g_w1);
    cudaGetSymbolAddress((void**)&at16,  g_at);
    cudaGetSymbolAddress((void**)&fe16,  g_fe);
    cudaGetSymbolAddress((void**)&hbuf,  g_h);

    cudaFuncSetAttribute(sgemm_tc, cudaFuncAttributeMaxDynamicSharedMemorySize,
                         GEMM_SMEM);
    cudaFuncSetAttribute(attn_tc, cudaFuncAttributeMaxDynamicSharedMemorySize,
                         ATTN_SMEM);

    cvt_all_kernel<<<(SEG3 + 255) / 256, 256>>>(F, Wqkv, Wout, w1, F16, wq, wo, w1h);

    // qkv = F @ Wqkv^T + bqkv -> fp16 (Q scaled 1/8)
    sgemm_tc<<<dim3(1536 / 128, BN / 64), 256, GEMM_SMEM>>>(
        F16, wq, bqkv, nullptr, nullptr, qkv16, 1, 512, 1536);
    // attention -> fp16 O
    attn_tc<<<dim3(Nn / QT, Bb * Hh), 192, ATTN_SMEM>>>(qkv16, at16);
    // fenh = F + O @ Wout^T + bout -> fp16
    sgemm_tc<<<dim3(512 / 128, BN / 64), 256, GEMM_SMEM>>>(
        at16, wo, bout, F, nullptr, fe16, 0, 512, 512);
    // h = fenh @ w1^T + b1 -> fp32
    sgemm_tc<<<dim3(512 / 128, BN / 64), 256, GEMM_SMEM>>>(
        fe16, w1h, b1, nullptr, hbuf, nullptr, 0, 512, 512);
    // fused LN -> GELU -> comp -> outer -> topk -> write
    ln_outer_topk_kernel<<<BN, 512>>>(hbuf, lng, lnb, w2, b2, F, tmpl, out);
}

// round 17
// speedup vs baseline: 1.1068x; 1.0129x over previous
#include <cuda_runtime.h>
#include <cuda_fp16.h>
#include <math.h>

#define Bb   8
#define Nn   576
#define Dd   512
#define Mm   16
#define Hh   8
#define BN   (Bb*Nn)      // 4608
#define KTOP 51

typedef unsigned long long u64;
typedef unsigned int u32;

__device__ __forceinline__ u32 smem_u32(const void* p) {
    u32 a; asm("{ .reg .u64 t; cvta.to.shared.u64 t, %1; cvt.u32.u64 %0, t; }"
               : "=r"(a) : "l"(p));
    return a;
}

// ---- mma.sync helpers (fp16 in, fp32 acc) ----
__device__ __forceinline__ void ldsm4(u32* r, u32 addr) {
    asm volatile("ldmatrix.sync.aligned.m8n8.x4.shared.b16 {%0,%1,%2,%3}, [%4];"
                 : "=r"(r[0]), "=r"(r[1]), "=r"(r[2]), "=r"(r[3]) : "r"(addr));
}
__device__ __forceinline__ void ldsm4t(u32* r, u32 addr) {
    asm volatile("ldmatrix.sync.aligned.m8n8.x4.trans.shared.b16 {%0,%1,%2,%3}, [%4];"
                 : "=r"(r[0]), "=r"(r[1]), "=r"(r[2]), "=r"(r[3]) : "r"(addr));
}
__device__ __forceinline__ void mma16816(float* c, const u32* a, const u32* b) {
    asm volatile(
        "mma.sync.aligned.m16n8k16.row.col.f32.f16.f16.f32 "
        "{%0,%1,%2,%3}, {%4,%5,%6,%7}, {%8,%9}, {%0,%1,%2,%3};"
        : "+f"(c[0]), "+f"(c[1]), "+f"(c[2]), "+f"(c[3])
        : "r"(a[0]), "r"(a[1]), "r"(a[2]), "r"(a[3]), "r"(b[0]), "r"(b[1]));
}
__device__ __forceinline__ u32 h2pack(float x, float y) {
    __half2 h = __floats2half2_rn(x, y);
    return *(u32*)&h;
}
// packed half2 exp2: one MUFU op, two exps, result is a ready PV fragment
__device__ __forceinline__ u32 ex2h2(float x, float y) {
    u32 r = h2pack(x, y);
    asm("ex2.approx.f16x2 %0, %0;" : "+r"(r));
    return r;
}

// ---- cp.async ----
__device__ __forceinline__ void cpa16(u32 saddr, const void* g) {
    asm volatile("cp.async.cg.shared.global [%0], [%1], 16;" :: "r"(saddr), "l"(g));
}
#define CP_COMMIT() asm volatile("cp.async.commit_group;" ::: "memory")
#define CP_WAIT0()  asm volatile("cp.async.wait_group 0;" ::: "memory")

// ---- scratch (fp16) ----
__device__ __half g_qkv[BN * 3 * Dd];   // qkv (Q pre-scaled 1/8)
__device__ __half g_F16[BN * Dd];
__device__ __half g_wq [3*Dd*Dd];
__device__ __half g_wo [Dd*Dd];
__device__ __half g_w1 [Dd*Dd];
__device__ __half g_at [BN * Dd];
__device__ __half g_fe [BN * Dd];
__device__ float  g_h  [BN * Dd];

// ============================================================
// One-launch fp32 -> fp16 convert over 4 tensors
// ============================================================
#define SEG0 589824
#define SEG1 (SEG0 + 196608)
#define SEG2 (SEG1 + 65536)
#define SEG3 (SEG2 + 65536)

__global__ __launch_bounds__(256) void cvt_all_kernel(
    const float* __restrict__ F,    const float* __restrict__ Wqkv,
    const float* __restrict__ Wout, const float* __restrict__ w1,
    __half* __restrict__ F16, __half* __restrict__ wq,
    __half* __restrict__ wo,  __half* __restrict__ w1h)
{
    int i = blockIdx.x * 256 + threadIdx.x;
    if (i >= SEG3) return;
    const float* src; __half* dst; int j;
    if (i < SEG0)      { src = F;    dst = F16; j = i; }
    else if (i < SEG1) { src = Wqkv; dst = wq;  j = i - SEG0; }
    else if (i < SEG2) { src = Wout; dst = wo;  j = i - SEG1; }
    else               { src = w1;   dst = w1h; j = i - SEG2; }
    float4 v = reinterpret_cast<const float4*>(src)[j];
    u32 h0 = h2pack(v.x, v.y), h1 = h2pack(v.z, v.w);
    reinterpret_cast<uint2*>(dst)[j] = make_uint2(h0, h1);
}

// ============================================================
// Tensor-core HGEMM: 64x128 tile, 256 threads (8 warps 2x4),
// 3 CTAs/SM (reg-capped), cp.async 2-stage, K-chunk 32, 80B rows.
// ============================================================
#define GROWB 80
#define GA_BYTES (64 * GROWB)
#define GB_OFF   GA_BYTES
#define GBUFSZ   (GA_BYTES + 128 * GROWB)
#define GEMM_SMEM (2 * GBUFSZ)

__global__ __launch_bounds__(256, 3) void sgemm_tc(
    const __half* __restrict__ A, const __half* __restrict__ B,
    const float* __restrict__ bias, const float* __restrict__ residual,
    float* __restrict__ C, __half* __restrict__ S16,
    int qsplit, int K, int N)
{
    extern __shared__ unsigned char smem[];
    const u32 sb = smem_u32(smem);

    const int tid = threadIdx.x;
    const int wid = tid >> 5, lid = tid & 31;
    const int rowBase = blockIdx.y * 64;
    const int colBase = blockIdx.x * 128;
    const int warp_m = (wid >> 2) * 32;
    const int warp_n = (wid & 3) * 32;

    const int lrow = tid >> 2;
    const int lc4  = tid & 3;
    const u32 soA  = (u32)lrow * GROWB + (u32)lc4 * 16;
    const u32 soB0 = GB_OFF + soA;
    const u32 soB1 = soB0 + 64u * GROWB;
    const char* pA  = (const char*)A + ((size_t)(rowBase + lrow) * K) * 2 + lc4 * 16;
    const char* pB0 = (const char*)B + ((size_t)(colBase + lrow) * K) * 2 + lc4 * 16;
    const char* pB1 = (const char*)B + ((size_t)(colBase + lrow + 64) * K) * 2 + lc4 * 16;

    const int a_row = warp_m + (lid & 15);
    const u32 a_kb  = (u32)(lid >> 4) * 16;
    const int b_n   = warp_n + (lid & 7) + ((lid >> 4) << 3);
    const u32 b_kb  = (u32)((lid >> 3) & 1) * 16;

    float acc[2][4][4];
    #pragma unroll
    for (int i = 0; i < 2; i++)
        #pragma unroll
        for (int j = 0; j < 4; j++)
            #pragma unroll
            for (int q = 0; q < 4; q++) acc[i][j][q] = 0.f;

    const int nChunk = K >> 5;
    {
        cpa16(sb + soA,  pA);
        cpa16(sb + soB0, pB0);
        cpa16(sb + soB1, pB1);
        CP_COMMIT();
    }

    for (int c = 0; c < nChunk; c++) {
        CP_WAIT0();
        __syncthreads();
        if (c + 1 < nChunk) {
            u32 d = sb + (u32)((c + 1) & 1) * GBUFSZ;
            size_t kb = (size_t)(c + 1) * 64;
            cpa16(d + soA,  pA  + kb);
            cpa16(d + soB0, pB0 + kb);
            cpa16(d + soB1, pB1 + kb);
            CP_COMMIT();
        }

        const u32 bufo = (u32)(c & 1) * GBUFSZ;
        #pragma unroll
        for (int ks = 0; ks < 2; ks++) {
            const u32 kso = (u32)ks * 32;
            u32 bfr[2][4];
            #pragma unroll
            for (int np = 0; np < 2; np++) {
                u32 ba = sb + bufo + GB_OFF + (u32)(b_n + np * 16) * GROWB + kso + b_kb;
                ldsm4(bfr[np], ba);
            }
            #pragma unroll
            for (int mt = 0; mt < 2; mt++) {
                u32 aa = sb + bufo + (u32)(a_row + mt * 16) * GROWB + kso + a_kb;
                u32 afr[4];
                ldsm4(afr, aa);
                #pragma unroll
                for (int nt = 0; nt < 4; nt++)
                    mma16816(acc[mt][nt], afr, &bfr[nt >> 1][(nt & 1) * 2]);
            }
        }
    }

    const int frow = lid >> 2;
    const int fcol = (lid & 3) * 2;
    #pragma unroll
    for (int mt = 0; mt < 2; mt++) {
        #pragma unroll
        for (int nt = 0; nt < 4; nt++) {
            int col = colBase + warp_n + nt * 8 + fcol;
            float2 bi = *reinterpret_cast<const float2*>(bias + col);
            #pragma unroll
            for (int half = 0; half < 2; half++) {
                int r = rowBase + warp_m + mt * 16 + frow + half * 8;
                float2 o;
                o.x = acc[mt][nt][half * 2 + 0] + bi.x;
                o.y = acc[mt][nt][half * 2 + 1] + bi.y;
                if (residual) {
                    float2 rv = *reinterpret_cast<const float2*>(residual + (size_t)r * N + col);
                    o.x += rv.x; o.y += rv.y;
                }
                if (C)
                    *reinterpret_cast<float2*>(C + (size_t)r * N + col) = o;
                if (S16) {
                    float sc = (qsplit && col < 512) ? 0.125f : 1.0f;
                    *reinterpret_cast<u32*>(S16 + (size_t)r * N + col) =
                        h2pack(o.x * sc, o.y * sc);
                }
            }
        }
    }
}

// ============================================================
// Tensor-core flash attention, fp16 + f16x2 packed exp
// (R16-passing, unchanged)
// ============================================================
#define ROWB 144
#define QT 96
#define KV_K 0
#define KV_V 9216
#define KVBUF 18432
#define AQ   (2 * KVBUF)
#define ATTN_SMEM (2 * KVBUF + 13824)

__global__ __launch_bounds__(192) void attn_tc(
    const __half* __restrict__ qkv, __half* __restrict__ oat)
{
    extern __shared__ unsigned char smem[];
    const u32 sb = smem_u32(smem);

    const int tid = threadIdx.x;
    const int wid = tid >> 5, lid = tid & 31;
    const int bh = blockIdx.y;
    const int b = bh >> 3, h = bh & 7;
    const int q0 = blockIdx.x * QT;
    const float L2E = 1.44269504f;

    const __half* qp = qkv + (size_t)(b * Nn + q0) * 1536 + h * 64;
    const __half* kp = qkv + (size_t)(b * Nn) * 1536 + 512  + h * 64;
    const __half* vp = qkv + (size_t)(b * Nn) * 1536 + 1024 + h * 64;

    for (int s = tid; s < 512; s += 192) {
        int row = s >> 3, c8 = s & 7;
        size_t go = (size_t)row * 1536 + c8 * 8;
        u32 so = sb + (u32)row * ROWB + (u32)c8 * 16;
        cpa16(so + KV_K, kp + go);
        cpa16(so + KV_V, vp + go);
    }
    #pragma unroll
    for (int it = 0; it < 4; it++) {
        int s = tid + it * 192;
        int row = s >> 3, c8 = s & 7;
        size_t go = (size_t)row * 1536 + c8 * 8;
        cpa16(sb + AQ + (u32)row * ROWB + (u32)c8 * 16, qp + go);
    }
    CP_COMMIT();
    CP_WAIT0();
    __syncthreads();

    u32 qf[4][4];
    {
        const int a_row = (wid << 4) + (lid & 15);
        const u32 a_kb = (u32)(lid >> 4) * 16;
        #pragma unroll
        for (int kt = 0; kt < 4; kt++)
            ldsm4(qf[kt], sb + AQ + (u32)a_row * ROWB + (u32)kt * 32 + a_kb);
    }

    float m_lo = -1e30f, m_hi = -1e30f, l_lo = 0.f, l_hi = 0.f;
    float oacc[8][4];
    #pragma unroll
    for (int j = 0; j < 8; j++)
        #pragma unroll
        for (int q = 0; q < 4; q++) oacc[j][q] = 0.f;

    const int kb_row = (lid & 7) + ((lid >> 4) << 3);
    const u32 kb_kb  = (u32)((lid >> 3) & 1) * 16;
    const int vb_key = (lid & 7) + (((lid >> 3) & 1) << 3);
    const u32 vb_db  = (u32)(lid >> 4) * 16;

    const int nChunk = Nn / 64;
    for (int c = 0; c < nChunk; c++) {
        if (c + 1 < nChunk) {
            const u32 nb = sb + (u32)((c + 1) & 1) * KVBUF;
            const int kc1 = (c + 1) * 64;
            for (int s = tid; s < 512; s += 192) {
                int row = s >> 3, c8 = s & 7;
                size_t go = (size_t)(kc1 + row) * 1536 + c8 * 8;
                u32 so = nb + (u32)row * ROWB + (u32)c8 * 16;
                cpa16(so + KV_K, kp + go);
                cpa16(so + KV_V, vp + go);
            }
        }
        CP_COMMIT();

        const u32 bufb = sb + (u32)(c & 1) * KVBUF;

        float sacc[8][4];
        #pragma unroll
        for (int j = 0; j < 8; j++)
            #pragma unroll
            for (int q = 0; q < 4; q++) sacc[j][q] = 0.f;

        #pragma unroll
        for (int kt = 0; kt < 4; kt++) {
            #pragma unroll
            for (int ng = 0; ng < 4; ng++) {
                u32 ka = bufb + KV_K + (u32)(ng * 16 + kb_row) * ROWB + (u32)kt * 32 + kb_kb;
                u32 kf[4];
                ldsm4(kf, ka);
                mma16816(sacc[2 * ng + 0], qf[kt], &kf[0]);
                mma16816(sacc[2 * ng + 1], qf[kt], &kf[2]);
            }
        }

        float mx_lo = -1e30f, mx_hi = -1e30f;
        #pragma unroll
        for (int j = 0; j < 8; j++) {
            mx_lo = fmaxf(mx_lo, fmaxf(sacc[j][0], sacc[j][1]));
            mx_hi = fmaxf(mx_hi, fmaxf(sacc[j][2], sacc[j][3]));
        }
        #pragma unroll
        for (int o = 1; o <= 2; o <<= 1) {
            mx_lo = fmaxf(mx_lo, __shfl_xor_sync(0xffffffffu, mx_lo, o));
            mx_hi = fmaxf(mx_hi, __shfl_xor_sync(0xffffffffu, mx_hi, o));
        }
        float mn_lo = fmaxf(m_lo, mx_lo), mn_hi = fmaxf(m_hi, mx_hi);
        float corr_lo = __expf(m_lo - mn_lo), corr_hi = __expf(m_hi - mn_hi);

        u32 pex[8][2];
        float rs_lo = 0.f, rs_hi = 0.f;
        #pragma unroll
        for (int j = 0; j < 8; j++) {
            pex[j][0] = ex2h2((sacc[j][0] - mn_lo) * L2E, (sacc[j][1] - mn_lo) * L2E);
            pex[j][1] = ex2h2((sacc[j][2] - mn_hi) * L2E, (sacc[j][3] - mn_hi) * L2E);
            float2 f0 = __half22float2(*reinterpret_cast<__half2*>(&pex[j][0]));
            float2 f1 = __half22float2(*reinterpret_cast<__half2*>(&pex[j][1]));
            rs_lo += f0.x + f0.y;
            rs_hi += f1.x + f1.y;
        }
        #pragma unroll
        for (int o = 1; o <= 2; o <<= 1) {
            rs_lo += __shfl_xor_sync(0xffffffffu, rs_lo, o);
            rs_hi += __shfl_xor_sync(0xffffffffu, rs_hi, o);
        }
        l_lo = l_lo * corr_lo + rs_lo;
        l_hi = l_hi * corr_hi + rs_hi;
        m_lo = mn_lo; m_hi = mn_hi;
        #pragma unroll
        for (int j = 0; j < 8; j++) {
            oacc[j][0] *= corr_lo; oacc[j][1] *= corr_lo;
            oacc[j][2] *= corr_hi; oacc[j][3] *= corr_hi;
        }

        #pragma unroll
        for (int kt = 0; kt < 4; kt++) {
            const int j0 = 2 * kt, j1 = 2 * kt + 1;
            u32 ap[4];
            ap[0] = pex[j0][0];
            ap[1] = pex[j0][1];
            ap[2] = pex[j1][0];
            ap[3] = pex[j1][1];
            #pragma unroll
            for (int ng = 0; ng < 4; ng++) {
                u32 va = bufb + KV_V + (u32)(kt * 16 + vb_key) * ROWB + (u32)ng * 32 + vb_db;
                u32 vf[4];
                ldsm4t(vf, va);
                mma16816(oacc[2 * ng + 0], ap, &vf[0]);
                mma16816(oacc[2 * ng + 1], ap, &vf[2]);
            }
        }

        CP_WAIT0();
        __syncthreads();
    }

    const float inv_lo = 1.f / l_lo, inv_hi = 1.f / l_hi;
    const int r_lo = q0 + (wid << 4) + (lid >> 2);
    const int cb = h * 64 + (lid & 3) * 2;
    #pragma unroll
    for (int j = 0; j < 8; j++) {
        int col = cb + j * 8;
        *reinterpret_cast<u32*>(oat + (size_t)(b * Nn + r_lo) * Dd + col) =
            h2pack(oacc[j][0] * inv_lo, oacc[j][1] * inv_lo);
        *reinterpret_cast<u32*>(oat + (size_t)(b * Nn + r_lo + 8) * Dd + col) =
            h2pack(oacc[j][2] * inv_hi, oacc[j][3] * inv_hi);
    }
}

// ============================================================
// FUSED: LayerNorm -> GELU -> comp -> outer -> top-51 -> write
// (R16-passing, unchanged)
// ============================================================
__global__ __launch_bounds__(512) void ln_outer_topk_kernel(
    const float* __restrict__ hsrc,
    const float* __restrict__ ln_g, const float* __restrict__ ln_b,
    const float* __restrict__ w2,  const float* __restrict__ b2,
    const float* __restrict__ F, const float* __restrict__ templates,
    float* __restrict__ out)
{
    __shared__ float s[512];
    __shared__ float Frow[512];
    __shared__ float red[32];
    __shared__ float cs[16];
    __shared__ float Qout[512 * 17];

    const int row = blockIdx.x;
    const int tid = threadIdx.x;
    const int m = tid >> 5, lid = tid & 31;

    float x = hsrc[(size_t)row * 512 + tid];
    s[tid] = x;
    Frow[tid] = F[(size_t)row * 512 + tid];

    float sum = x, sq = x * x;
    #pragma unroll
    for (int o = 16; o >= 1; o >>= 1) {
        sum += __shfl_xor_sync(0xffffffffu, sum, o);
        sq  += __shfl_xor_sync(0xffffffffu, sq,  o);
    }
    if (lid == 0) { red[m] = sum; red[m + 16] = sq; }
    __syncthreads();
    if (tid == 0) {
        float S = 0.f, Q = 0.f;
        #pragma unroll
        for (int i = 0; i < 16; i++) { S += red[i]; Q += red[i + 16]; }
        red[0] = S * (1.f / 512.f);
        red[16] = Q * (1.f / 512.f);
    }
    __syncthreads();
    const float mean = red[0];
    const float rstd = rsqrtf(red[16] - mean * mean + 1e-5f);

    float g = (x - mean) * rstd * ln_g[tid] + ln_b[tid];
    g = 0.5f * g * (1.f + erff(g * 0.70710678118f));
    __syncthreads();
    s[tid] = g;
    __syncthreads();

    {
        float p = 0.f;
        const float* wrow = w2 + m * 512;
        #pragma unroll
        for (int i = 0; i < 16; i++) {
            int e = lid + 32 * i;
            p += s[e] * wrow[e];
        }
        #pragma unroll
        for (int o = 16; o >= 1; o >>= 1)
            p += __shfl_xor_sync(0xffffffffu, p, o);
        if (lid == 0) cs[m] = p + b2[m];
    }
    __syncthreads();

    const float c = cs[m];
    float    qv[16];
    unsigned key[16];
    unsigned mx = 0;
    #pragma unroll
    for (int i = 0; i < 16; i++) {
        int d = lid + 32 * i;
        float q = Frow[d] * templates[m * 512 + d] * c;
        qv[i]  = q;
        key[i] = __float_as_uint(fabsf(q));
        mx = max(mx, key[i]);
    }
    #pragma unroll
    for (int o = 16; o >= 1; o >>= 1)
        mx = max(mx, __shfl_xor_sync(0xffffffffu, mx, o));

    unsigned prefix = 0;
    int bit = 31 - __clz(mx | 1u);
    for (; bit >= 0; bit--) {
        unsigned test = prefix | (1u << bit);
        int cnt = 0;
        #pragma unroll
        for (int i = 0; i < 16; i++) cnt += (key[i] >= test);
        cnt = __reduce_add_sync(0xffffffffu, cnt);
        if (cnt >= KTOP) {
            prefix = test;
            if (cnt == KTOP) break;
        }
    }

    #pragma unroll
    for (int i = 0; i < 16; i++) {
        int d = lid + 32 * i;
        Qout[d * 17 + m] = (key[i] >= prefix) ? qv[i] : 0.f;
    }
    __syncthreads();

    float* ob = out + (size_t)row * (512 * 16);
    #pragma unroll
    for (int i = 0; i < 16; i++) {
        int e = tid + 512 * i;
        ob[e] = Qout[(e >> 4) * 17 + (e & 15)];
    }
}

// ============================================================
extern "C" void kernel_launch(void* const* d_in, const int* in_sizes, int n_in,
                              void* d_out, int out_size) {
    const float* F    = (const float*)d_in[0];
    const float* Wqkv = (const float*)d_in[1];
    const float* bqkv = (const float*)d_in[2];
    const float* Wout = (const float*)d_in[3];
    const float* bout = (const float*)d_in[4];
    const float* w1   = (const float*)d_in[5];
    const float* b1   = (const float*)d_in[6];
    const float* lng  = (const float*)d_in[7];
    const float* lnb  = (const float*)d_in[8];
    const float* w2   = (const float*)d_in[9];
    const float* b2   = (const float*)d_in[10];
    const float* tmpl = (const float*)d_in[11];
    float* out = (float*)d_out;

    __half *qkv16, *F16, *wq, *wo, *w1h, *at16, *fe16;
    float *hbuf;
    cudaGetSymbolAddress((void**)&qkv16, g_qkv);
    cudaGetSymbolAddress((void**)&F16,   g_F16);
    cudaGetSymbolAddress((void**)&wq,    g_wq);
    cudaGetSymbolAddress((void**)&wo,    g_wo);
    cudaGetSymbolAddress((void**)&w1h,   g_w1);
    cudaGetSymbolAddress((void**)&at16,  g_at);
    cudaGetSymbolAddress((void**)&fe16,  g_fe);
    cudaGetSymbolAddress((void**)&hbuf,  g_h);

    cudaFuncSetAttribute(sgemm_tc, cudaFuncAttributeMaxDynamicSharedMemorySize,
                         GEMM_SMEM);
    cudaFuncSetAttribute(attn_tc, cudaFuncAttributeMaxDynamicSharedMemorySize,
                         ATTN_SMEM);

    cvt_all_kernel<<<(SEG3 + 255) / 256, 256>>>(F, Wqkv, Wout, w1, F16, wq, wo, w1h);

    // qkv = F @ Wqkv^T + bqkv -> fp16 (Q scaled 1/8)
    sgemm_tc<<<dim3(1536 / 128, BN / 64), 256, GEMM_SMEM>>>(
        F16, wq, bqkv, nullptr, nullptr, qkv16, 1, 512, 1536);
    // attention -> fp16 O
    attn_tc<<<dim3(Nn / QT, Bb * Hh), 192, ATTN_SMEM>>>(qkv16, at16);
    // fenh = F + O @ Wout^T + bout -> fp16
    sgemm_tc<<<dim3(512 / 128, BN / 64), 256, GEMM_SMEM>>>(
        at16, wo, bout, F, nullptr, fe16, 0, 512, 512);
    // h = fenh @ w1^T + b1 -> fp32
    sgemm_tc<<<dim3(512 / 128, BN / 64), 256, GEMM_SMEM>>>(
        fe16, w1h, b1, nullptr, hbuf, nullptr, 0, 512, 512);
    // fused LN -> GELU -> comp -> outer -> topk -> write
    ln_outer_topk_kernel<<<BN, 512>>>(hbuf, lng, lnb, w2, b2, F, tmpl, out);
}